// round 15
// baseline (speedup 1.0000x reference)
#include <cuda_runtime.h>
#include <cuda_fp16.h>
#include <cstdint>

// v2 artifact (renamed/reorganized; algorithm identical to R13 proposal).
// Fused: out = leaky( [x_up, leaky(gather(x_down) @ W_lin + b_lin)] @ W_fus + b_fus )
// B=4, N_down=16384, N_up=65536, C_down=256, C_up=128, C_out=128. M=262144.
// Per CTA: 64 rows x 128 cols, 2 CTAs/SM. fp16 mma.sync.m16n8k16 (fp32 accum).
// A tiles fp32 via cp.async (gather), half-converted at fragment load.
// B tiles pre-transposed half [n][k] via cp.async. Unroll-1 double-buffered pipeline.

#define BM 64
#define KC 64
#define N_DOWN 16384
#define C_DOWN 256
#define C_UP   128
#define LOG2_NUP 16

#define SA_STRIDE 72      // floats per A row (64 data + 8 pad)
#define B_STRH 72         // halves per B row (64 data + 8 pad)
#define X_STRH 136        // halves per sX row (128 data + 8 pad)

// byte offsets in dynamic smem
#define SA_B(b) ((b) * (BM * SA_STRIDE * 4))                         // 2 x 18432
#define SB_B(b) (2 * BM * SA_STRIDE * 4 + (b) * (128 * B_STRH * 2))  // 2 x 18432
#define SX_B    (2 * BM * SA_STRIDE * 4 + 2 * 128 * B_STRH * 2)      // 73728
#define SBIAS_B (SX_B + BM * X_STRH * 2)                             // 91136
#define SROW_B  (SBIAS_B + 256 * 4)                                  // 92160
#define SMEM_BYTES (SROW_B + BM * 4)                                 // 92416

__device__ __half g_WlinT_v2[C_UP * C_DOWN];    // [n][k] half
__device__ __half g_WfusT_v2[C_UP * 2 * C_UP];  // [n][k] half

__device__ __forceinline__ float lrelu01(float v) { return fmaxf(v, 0.1f * v); }

__device__ __forceinline__ unsigned packh2(float lo, float hi) {
    unsigned r;
    asm("cvt.rn.f16x2.f32 %0, %1, %2;" : "=r"(r) : "f"(hi), "f"(lo));
    return r;
}
__device__ __forceinline__ void cpa16(uint32_t sdst, const void* gsrc) {
    asm volatile("cp.async.cg.shared.global [%0], [%1], 16;" :: "r"(sdst), "l"(gsrc));
}
__device__ __forceinline__ void cpa_commit() { asm volatile("cp.async.commit_group;"); }

__device__ __forceinline__ void hmma16816(float c[4], const unsigned a[4], const unsigned b[2]) {
    asm volatile("mma.sync.aligned.m16n8k16.row.col.f32.f16.f16.f32 "
                 "{%0,%1,%2,%3}, {%4,%5,%6,%7}, {%8,%9}, {%0,%1,%2,%3};"
                 : "+f"(c[0]), "+f"(c[1]), "+f"(c[2]), "+f"(c[3])
                 : "r"(a[0]), "r"(a[1]), "r"(a[2]), "r"(a[3]),
                   "r"(b[0]), "r"(b[1]));
}

// acc += A[64x64](fp32 smem, converted on load) @ B[n][k](half smem)
__device__ __forceinline__ void gemm_chunk_f32A(
    const float* __restrict__ Ab, const __half* __restrict__ Bb,
    float acc[2][4][4], int wm, int wn, int g, int t)
{
#pragma unroll
    for (int kk = 0; kk < KC; kk += 16) {
        unsigned a[2][4];
#pragma unroll
        for (int mi = 0; mi < 2; mi++) {
            const float* ap = Ab + (wm * 32 + mi * 16 + g) * SA_STRIDE + kk + 2 * t;
            float2 p0 = *(const float2*)(ap);
            float2 p1 = *(const float2*)(ap + 8 * SA_STRIDE);
            float2 p2 = *(const float2*)(ap + 8);
            float2 p3 = *(const float2*)(ap + 8 * SA_STRIDE + 8);
            a[mi][0] = packh2(p0.x, p0.y);
            a[mi][1] = packh2(p1.x, p1.y);
            a[mi][2] = packh2(p2.x, p2.y);
            a[mi][3] = packh2(p3.x, p3.y);
        }
        unsigned bb[4][2];
#pragma unroll
        for (int ni = 0; ni < 4; ni++) {
            const __half* bp = Bb + (wn * 32 + ni * 8 + g) * B_STRH + kk + 2 * t;
            bb[ni][0] = *(const unsigned*)(bp);
            bb[ni][1] = *(const unsigned*)(bp + 8);
        }
#pragma unroll
        for (int mi = 0; mi < 2; mi++)
#pragma unroll
            for (int ni = 0; ni < 4; ni++)
                hmma16816(acc[mi][ni], a[mi], bb[ni]);
    }
}

// acc += sX[64x64 half slice] @ B[n][k](half smem)
__device__ __forceinline__ void gemm_chunk_h16A(
    const __half* __restrict__ Ab, const __half* __restrict__ Bb,
    float acc[2][4][4], int wm, int wn, int g, int t)
{
#pragma unroll
    for (int kk = 0; kk < KC; kk += 16) {
        unsigned a[2][4];
#pragma unroll
        for (int mi = 0; mi < 2; mi++) {
            const __half* ap = Ab + (wm * 32 + mi * 16 + g) * X_STRH + kk + 2 * t;
            a[mi][0] = *(const unsigned*)(ap);
            a[mi][1] = *(const unsigned*)(ap + 8 * X_STRH);
            a[mi][2] = *(const unsigned*)(ap + 8);
            a[mi][3] = *(const unsigned*)(ap + 8 * X_STRH + 8);
        }
        unsigned bb[4][2];
#pragma unroll
        for (int ni = 0; ni < 4; ni++) {
            const __half* bp = Bb + (wn * 32 + ni * 8 + g) * B_STRH + kk + 2 * t;
            bb[ni][0] = *(const unsigned*)(bp);
            bb[ni][1] = *(const unsigned*)(bp + 8);
        }
#pragma unroll
        for (int mi = 0; mi < 2; mi++)
#pragma unroll
            for (int ni = 0; ni < 4; ni++)
                hmma16816(acc[mi][ni], a[mi], bb[ni]);
    }
}

// cp.async chunk c into buffer (c&1). 0-3: gather A + WlinT. 4-5: x_up A + WfusT.
// 6-7: WfusT only (A comes from sX).
__device__ __forceinline__ void stage_chunk(
    int c, uint32_t sbase,
    const float* __restrict__ x_down, const float* __restrict__ x_up,
    const int* __restrict__ sRow, long long m0, int tid)
{
    const int kc = (c < 4) ? c * KC : (c - 4) * KC;

    if (c < 6) {
        uint32_t ab = sbase + SA_B(c & 1);
#pragma unroll
        for (int i = 0; i < 4; i++) {               // A: 64 rows x 16 float4
            int lin = tid + i * 256;
            int row = lin >> 4, f4 = lin & 15;
            const float* src = (c < 4)
                ? x_down + (size_t)sRow[row] * C_DOWN + kc + f4 * 4
                : x_up + (size_t)(m0 + row) * C_UP + kc + f4 * 4;
            cpa16(ab + (uint32_t)(row * SA_STRIDE + f4 * 4) * 4, src);
        }
    }
    {
        uint32_t bbase = sbase + SB_B(c & 1);
        const __half* W = (c < 4) ? g_WlinT_v2 : g_WfusT_v2;
        const int kt = (c < 4) ? C_DOWN : 2 * C_UP;
#pragma unroll
        for (int i = 0; i < 4; i++) {               // B: 128 n-rows x 8 units of 8 halves
            int lin = tid + i * 256;
            int n = lin >> 3, u = lin & 7;
            cpa16(bbase + (uint32_t)(n * B_STRH + u * 8) * 2,
                  W + (size_t)n * kt + kc + u * 8);
        }
    }
}

__global__ void prep_weights_v2(const float* __restrict__ Wl, const float* __restrict__ Wf) {
    int i = blockIdx.x * 256 + threadIdx.x;       // 32768 threads cover 256x128
    if (i < C_DOWN * C_UP) {
        int k = i >> 7, n = i & 127;
        g_WlinT_v2[n * C_DOWN + k]   = __float2half_rn(Wl[i]);
        g_WfusT_v2[n * 2 * C_UP + k] = __float2half_rn(Wf[i]);
    }
}

__global__ void __launch_bounds__(256, 2)
upsampling_f16_v2_kernel(const float* __restrict__ x_down,
                         const float* __restrict__ x_up,
                         const int* __restrict__ up_idx,
                         const float* __restrict__ b_lin,
                         const float* __restrict__ b_fus,
                         float* __restrict__ out)
{
    extern __shared__ __align__(16) char smc[];
    __half* sX   = (__half*)(smc + SX_B);
    float* sBias = (float*)(smc + SBIAS_B);
    int*   sRow  = (int*)(smc + SROW_B);
    uint32_t sbase;
    asm("{ .reg .u64 t; cvta.to.shared.u64 t, %1; cvt.u32.u64 %0, t; }" : "=r"(sbase) : "l"(smc));

    const int tid  = threadIdx.x;
    const int lane = tid & 31;
    const int warp = tid >> 5;
    const int wm = warp >> 2, wn = warp & 3;
    const int g = lane >> 2, t = lane & 3;

    const long long m0 = (long long)blockIdx.x * BM;
    const int bidx = (int)(m0 >> LOG2_NUP);

    if (tid < BM) {
        int idx = up_idx[m0 + tid];
        idx = max(0, min(idx, N_DOWN - 1));
        sRow[tid] = bidx * N_DOWN + idx;
    }
    if (tid < 128) {
        sBias[tid]       = b_lin[tid];
        sBias[128 + tid] = b_fus[tid];
    }

    float acc[2][4][4];
#pragma unroll
    for (int mi = 0; mi < 2; mi++)
#pragma unroll
        for (int ni = 0; ni < 4; ni++)
#pragma unroll
            for (int q = 0; q < 4; q++) acc[mi][ni][q] = 0.0f;

    __syncthreads();   // sRow/sBias ready

    stage_chunk(0, sbase, x_down, x_up, sRow, m0, tid); cpa_commit();
    stage_chunk(1, sbase, x_down, x_up, sRow, m0, tid); cpa_commit();

#pragma unroll 1
    for (int c = 0; c < 8; c++) {
        if (c < 7) asm volatile("cp.async.wait_group 1;");
        else       asm volatile("cp.async.wait_group 0;");
        __syncthreads();                               // chunk c visible

        const __half* Bb = (const __half*)(smc + SB_B(c & 1));
        if (c < 6)
            gemm_chunk_f32A((const float*)(smc + SA_B(c & 1)), Bb, acc, wm, wn, g, t);
        else
            gemm_chunk_h16A(sX + (c - 6) * KC, Bb, acc, wm, wn, g, t);

        if (c == 3) {
            // Epilogue 1: bias + leaky -> sX (half), reset acc for GEMM2.
#pragma unroll
            for (int mi = 0; mi < 2; mi++) {
                int r0 = wm * 32 + mi * 16 + g;
#pragma unroll
                for (int ni = 0; ni < 4; ni++) {
                    int cc = wn * 32 + ni * 8 + 2 * t;
                    float bz0 = sBias[cc], bz1 = sBias[cc + 1];
                    *(unsigned*)(sX + r0 * X_STRH + cc) =
                        packh2(lrelu01(acc[mi][ni][0] + bz0), lrelu01(acc[mi][ni][1] + bz1));
                    *(unsigned*)(sX + (r0 + 8) * X_STRH + cc) =
                        packh2(lrelu01(acc[mi][ni][2] + bz0), lrelu01(acc[mi][ni][3] + bz1));
                    acc[mi][ni][0] = acc[mi][ni][1] = acc[mi][ni][2] = acc[mi][ni][3] = 0.0f;
                }
            }
        }
        __syncthreads();                               // buffer (c&1) free; sX ready (c==3)
        if (c + 2 < 8) {
            stage_chunk(c + 2, sbase, x_down, x_up, sRow, m0, tid);
            cpa_commit();
        }
    }

    // Epilogue 2: bias + leaky -> out (fp32)
#pragma unroll
    for (int mi = 0; mi < 2; mi++) {
        int r0 = wm * 32 + mi * 16 + g;
#pragma unroll
        for (int ni = 0; ni < 4; ni++) {
            int cc = wn * 32 + ni * 8 + 2 * t;
            float bz0 = sBias[128 + cc], bz1 = sBias[129 + cc];
            float2 v0, v1;
            v0.x = lrelu01(acc[mi][ni][0] + bz0);
            v0.y = lrelu01(acc[mi][ni][1] + bz1);
            v1.x = lrelu01(acc[mi][ni][2] + bz0);
            v1.y = lrelu01(acc[mi][ni][3] + bz1);
            *(float2*)(out + (size_t)(m0 + r0) * C_UP + cc)     = v0;
            *(float2*)(out + (size_t)(m0 + r0 + 8) * C_UP + cc) = v1;
        }
    }
}

extern "C" void kernel_launch(void* const* d_in, const int* in_sizes, int n_in,
                              void* d_out, int out_size)
{
    const float* x_down = (const float*)d_in[0];
    const float* x_up   = (const float*)d_in[1];
    const int*   up_idx = (const int*)d_in[2];
    const float* W_lin  = (const float*)d_in[3];
    const float* b_lin  = (const float*)d_in[4];
    const float* W_fus  = (const float*)d_in[5];
    const float* b_fus  = (const float*)d_in[6];
    float*       out    = (float*)d_out;

    const int grid = in_sizes[2] / BM;   // 262144 / 64 = 4096

    static bool attr_done = false;
    if (!attr_done) {
        cudaFuncSetAttribute(upsampling_f16_v2_kernel,
                             cudaFuncAttributeMaxDynamicSharedMemorySize, SMEM_BYTES);
        attr_done = true;
    }

    prep_weights_v2<<<128, 256>>>(W_lin, W_fus);
    upsampling_f16_v2_kernel<<<grid, 256, SMEM_BYTES>>>(
        x_down, x_up, up_idx, b_lin, b_fus, out);
}